// round 16
// baseline (speedup 1.0000x reference)
#include <cuda_runtime.h>
#include <cuda_fp16.h>
#include <cstdint>

#define NB    8
#define CIN   128
#define SP    1600
#define NHEAD 8
#define HD    16

typedef unsigned long long u64;

// f16x2 word: first arg -> low 16 bits, second -> high 16 bits
__device__ __forceinline__ uint32_t f16x2_of(float lo, float hi) {
    uint32_t r;
    asm("cvt.rn.f16x2.f32 %0, %1, %2;" : "=r"(r) : "f"(hi), "f"(lo));
    return r;
}
__device__ __forceinline__ void f16x2_to_f32(uint32_t w, float& lo, float& hi) {
    asm("{ .reg .b16 l, h; mov.b32 {l, h}, %2; cvt.f32.f16 %0, l; cvt.f32.f16 %1, h; }"
        : "=f"(lo), "=f"(hi) : "r"(w));
}
__device__ __forceinline__ u64 packh2(float a, float b) {
    uint32_t hw = f16x2_of(a, b);
    float ha, hb;
    f16x2_to_f32(hw, ha, hb);
    uint32_t lw = f16x2_of(a - ha, b - hb);
    return (u64)hw | ((u64)lw << 32);
}
__device__ __forceinline__ uint32_t ex2h2(uint32_t w) {
    uint32_t r; asm("ex2.approx.f16x2 %0, %1;" : "=r"(r) : "r"(w)); return r;
}
__device__ __forceinline__ uint32_t hadd2(uint32_t a, uint32_t b) {
    uint32_t r; asm("add.rn.f16x2 %0, %1, %2;" : "=r"(r) : "r"(a), "r"(b)); return r;
}

// warp mma: D += A(f16 16x16) * B(f16 16x8), f32 accum
__device__ __forceinline__ void mmaf16(float* d, const uint32_t* a, uint32_t b0, uint32_t b1) {
    asm volatile("mma.sync.aligned.m16n8k16.row.col.f32.f16.f16.f32 "
        "{%0,%1,%2,%3},{%4,%5,%6,%7},{%8,%9},{%0,%1,%2,%3};"
        : "+f"(d[0]), "+f"(d[1]), "+f"(d[2]), "+f"(d[3])
        : "r"(a[0]), "r"(a[1]), "r"(a[2]), "r"(a[3]), "r"(b0), "r"(b1));
}

// Scratch:
__device__ uint2      g_wp[(size_t)384 * 8 * 4];         // W_qkv f16 frags, PERMUTED rows
__device__ uint2      g_wop[(size_t)128 * 8 * 4];        // W_o   f16 frags, PERMUTED rows
__device__ ulonglong2 g_xp[(size_t)NB * SP * 8 * 4];     // X hi/lo frags [n][tok][ks][t]
__device__ ulonglong2 g_op[(size_t)NB * SP * 8 * 4];     // attn-out hi/lo frags [n][tok][ks=h][t]
__device__ uint32_t   g_qpk[(size_t)64 * 8 * SP + 64];   // Q f16x2 [nh][dpair][s]
__device__ u64        g_kp2[(size_t)64 * SP * 4];        // K frag words [nh][tok][4]
__device__ u64        g_vp2[(size_t)64 * 100 * 16 * 4];  // V frag words [nh][kt][dim][4]
__device__ float2     g_pnum[(size_t)2 * 64 * 8 * SP];   // partial numerators [z][nh][cp][s]
__device__ float      g_pden[(size_t)2 * 64 * SP];       // partial denominators [z][nh][s]

// ===================================================================
// Single conversion kernel: W_qkv + W_o (permuted rows) and X frags.
// ===================================================================
#define W_ITEMS (512 * 8)
#define X_ITEMS (NB * 8 * SP)

__global__ void conv_all(const float* __restrict__ Wq, const float* __restrict__ Wo,
                         const float* __restrict__ X) {
    int idx = blockIdx.x * 256 + threadIdx.x;
    if (idx < W_ITEMS) {
        int ks = idx & 7, r = idx >> 3;
        const float* W;
        uint2* dst;
        int rl;
        if (r < 384) { W = Wq; dst = g_wp;  rl = r; }
        else         { W = Wo; dst = g_wop; rl = r - 384; }
        int tile = rl >> 4, rr = rl & 15;
        int o = tile * 16 + ((rr < 8) ? 2 * rr : 2 * (rr - 8) + 1);
        const float* wr = W + (size_t)o * CIN + 16 * ks;
        uint2 out[4];
        #pragma unroll
        for (int t = 0; t < 4; t++) {
            out[t].x = f16x2_of(wr[2 * t],     wr[2 * t + 1]);
            out[t].y = f16x2_of(wr[2 * t + 8], wr[2 * t + 9]);
        }
        uint2* d = dst + ((size_t)rl * 8 + ks) * 4;
        d[0] = out[0]; d[1] = out[1]; d[2] = out[2]; d[3] = out[3];
    } else {
        int xi = idx - W_ITEMS;
        if (xi >= X_ITEMS) return;
        int s = xi % SP;
        int rest = xi / SP;
        int ks = rest & 7, n = rest >> 3;
        const float* xb = X + ((size_t)n * CIN + 16 * ks) * SP + s;
        ulonglong2 out[4];
        #pragma unroll
        for (int t = 0; t < 4; t++) {
            out[t].x = packh2(xb[(size_t)(2 * t) * SP],     xb[(size_t)(2 * t + 1) * SP]);
            out[t].y = packh2(xb[(size_t)(2 * t + 8) * SP], xb[(size_t)(2 * t + 9) * SP]);
        }
        ulonglong2* d = g_xp + ((size_t)(n * SP + s) * 8 + ks) * 4;
        d[0] = out[0]; d[1] = out[1]; d[2] = out[2]; d[3] = out[3];
    }
}

// ===================================================================
// Shared mainloop: X tile staged in SMEM (32KB), 2-term fp16 MMA.
// ===================================================================
__device__ __forceinline__ void proj_mainloop(
    char* sbuf, const uint2* __restrict__ Wf, const ulonglong2* __restrict__ Xf,
    int n, int s0, int o0, int tid, float d[8][4])
{
    const int warp = tid >> 5, lane = tid & 31;
    const int g = lane >> 2, t = lane & 3;

    ulonglong2* Xs = (ulonglong2*)sbuf;
    const ulonglong2* src = Xf + (size_t)(n * SP + s0) * 32;
    #pragma unroll
    for (int i = 0; i < 16; i++)
        Xs[tid + i * 128] = src[tid + i * 128];
    __syncthreads();

    const int r1 = o0 + warp * 16 + g;
    const int r2 = r1 + 8;

    #pragma unroll
    for (int ks = 0; ks < 8; ks++) {
        uint2 wa = Wf[((size_t)r1 * 8 + ks) * 4 + t];
        uint2 wb = Wf[((size_t)r2 * 8 + ks) * 4 + t];
        uint32_t ah[4] = {wa.x, wb.x, wa.y, wb.y};

        #pragma unroll
        for (int nb = 0; nb < 8; nb++) {
            ulonglong2 xv = Xs[((nb * 8 + g) * 8 + ks) * 4 + t];
            mmaf16(d[nb], ah, (uint32_t)xv.x, (uint32_t)xv.y);
            mmaf16(d[nb], ah, (uint32_t)(xv.x >> 32), (uint32_t)(xv.y >> 32));
        }
    }
}

// ===================================================================
// QKV projection: register-direct pack epilogue.
// ===================================================================
__global__ __launch_bounds__(128) void proj_qkv_mma(void) {
    __shared__ __align__(16) char sbuf[32768];

    const int n  = blockIdx.z;
    const int s0 = blockIdx.x * 64;
    const int o0 = blockIdx.y * 64;
    const int tid = threadIdx.x;
    const int warp = tid >> 5, lane = tid & 31;
    const int g = lane >> 2, t = lane & 3;

    float d[8][4];
    #pragma unroll
    for (int nb = 0; nb < 8; nb++)
        #pragma unroll
        for (int j = 0; j < 4; j++) d[nb][j] = 0.f;

    proj_mainloop(sbuf, g_wp, g_xp, n, s0, o0, tid, d);

    const float qs = 0.25f * 1.4426950408889634f;
    const int o_even = o0 + warp * 16 + 2 * g;
    const int hh = o_even / 48;
    const int within = o_even - hh * 48;
    const int nhI = n * 8 + hh;

    if (within < 16) {
        int dp = within >> 1;
        uint32_t* dst = g_qpk + ((size_t)nhI * 8 + dp) * SP;
        #pragma unroll
        for (int nb = 0; nb < 8; nb++) {
            int sa = s0 + nb * 8 + 2 * t;
            uint2 w;
            w.x = f16x2_of(d[nb][0] * qs, d[nb][2] * qs);
            w.y = f16x2_of(d[nb][1] * qs, d[nb][3] * qs);
            *(uint2*)(dst + sa) = w;
        }
    } else if (within < 32) {
        int dp = (within - 16) >> 1;
        int off = (dp & 3) * 2 + (dp >> 2);
        uint32_t* kb = (uint32_t*)g_kp2 + (size_t)nhI * SP * 8 + off;
        #pragma unroll
        for (int nb = 0; nb < 8; nb++) {
            int sa = s0 + nb * 8 + 2 * t;
            kb[(size_t)sa * 8]       = f16x2_of(d[nb][0], d[nb][2]);
            kb[(size_t)(sa + 1) * 8] = f16x2_of(d[nb][1], d[nb][3]);
        }
    } else {
        int dl = within - 32;
        uint32_t* vb = (uint32_t*)g_vp2 + (size_t)nhI * 100 * 128;
        #pragma unroll
        for (int nb = 0; nb < 8; nb++) {
            int tok = s0 + nb * 8 + 2 * t;
            int kt  = tok >> 4;
            int kpl = (tok >> 1) & 7;
            size_t base = (size_t)kt * 128 + (size_t)(kpl & 3) * 2 + (kpl >> 2);
            vb[base + (size_t)dl * 8]       = f16x2_of(d[nb][0], d[nb][1]);
            vb[base + (size_t)(dl + 1) * 8] = f16x2_of(d[nb][2], d[nb][3]);
        }
    }
}

// ===================================================================
// Output projection: permuted-row Ys staging + bias epilogue.
// ===================================================================
__global__ __launch_bounds__(128) void proj_out_mma(const float* __restrict__ bias,
                                                    float* __restrict__ Y) {
    __shared__ __align__(16) char sbuf[32768];

    const int n  = blockIdx.z;
    const int s0 = blockIdx.x * 64;
    const int o0 = blockIdx.y * 64;
    const int tid = threadIdx.x;
    const int warp = tid >> 5, lane = tid & 31;
    const int g = lane >> 2, t = lane & 3;

    float d[8][4];
    #pragma unroll
    for (int nb = 0; nb < 8; nb++)
        #pragma unroll
        for (int j = 0; j < 4; j++) d[nb][j] = 0.f;

    proj_mainloop(sbuf, g_wop, g_op, n, s0, o0, tid, d);
    __syncthreads();

    float (*Ys)[68] = (float(*)[68])sbuf;
    #pragma unroll
    for (int nb = 0; nb < 8; nb++) {
        int ol = warp * 16 + 2 * g;
        int sl = nb * 8 + 2 * t;
        Ys[ol][sl]     = d[nb][0];
        Ys[ol][sl + 1] = d[nb][1];
        Ys[ol + 1][sl]     = d[nb][2];
        Ys[ol + 1][sl + 1] = d[nb][3];
    }
    __syncthreads();

    const int tx = tid & 15, ty = tid >> 4;
    #pragma unroll
    for (int r = 0; r < 8; r++) {
        int olo = ty * 8 + r;
        int o = o0 + olo;
        float b = bias[o];
        float4 v = *(const float4*)&Ys[olo][tx * 4];
        v.x += b; v.y += b; v.z += b; v.w += b;
        *(float4*)(Y + ((size_t)n * CIN + o) * SP + s0 + tx * 4) = v;
    }
}

// ===================================================================
// Attention, key-split; l via HADD2 tree (no ones-MMA).
// ===================================================================
__global__ __launch_bounds__(128) void attn_mma(void) {
    const int tid  = threadIdx.x;
    const int warp = tid >> 5, lane = tid & 31;
    const int g = lane >> 2, t = lane & 3;
    const int nh = blockIdx.y;
    const int z  = blockIdx.z;
    const int q0 = blockIdx.x * 128 + warp * 32;

    const uint32_t* qp = g_qpk + (size_t)nh * 8 * SP;
    const u64* kp2 = g_kp2 + (size_t)nh * SP * 4;
    const u64* vp2 = g_vp2 + (size_t)nh * 100 * 64;

    uint32_t aq0[4], aq1[4];
    {
        const uint32_t* q1 = qp + (size_t)t * SP;
        const uint32_t* q2 = qp + (size_t)(t + 4) * SP;
        aq0[0] = q1[q0 + g];      aq0[1] = q1[q0 + 8 + g];
        aq0[2] = q2[q0 + g];      aq0[3] = q2[q0 + 8 + g];
        aq1[0] = q1[q0 + 16 + g]; aq1[1] = q1[q0 + 24 + g];
        aq1[2] = q2[q0 + 16 + g]; aq1[3] = q2[q0 + 24 + g];
    }

    float dA0[4] = {0,0,0,0}, dA1[4] = {0,0,0,0};
    float dB0[4] = {0,0,0,0}, dB1[4] = {0,0,0,0};
    float lsA0 = 0.f, lsA1 = 0.f, lsB0 = 0.f, lsB1 = 0.f;

    const int kt0 = z * 50;
    const u64* kA_p = kp2 + (size_t)kt0 * 64 + (size_t)g * 4 + t;
    const u64* kB_p = kp2 + (size_t)kt0 * 64 + (size_t)(8 + g) * 4 + t;
    const u64* vA_p = vp2 + (size_t)kt0 * 64 + (size_t)g * 4 + t;
    const u64* vB_p = vp2 + (size_t)kt0 * 64 + (size_t)(8 + g) * 4 + t;

    #pragma unroll 2
    for (int it = 0; it < 50; it++) {
        u64 kA = *kA_p, kB = *kB_p;
        kA_p += 64; kB_p += 64;

        float s00[4] = {0,0,0,0}, s01[4] = {0,0,0,0};
        float s10[4] = {0,0,0,0}, s11[4] = {0,0,0,0};
        mmaf16(s00, aq0, (uint32_t)kA, (uint32_t)(kA >> 32));
        mmaf16(s01, aq0, (uint32_t)kB, (uint32_t)(kB >> 32));
        mmaf16(s10, aq1, (uint32_t)kA, (uint32_t)(kA >> 32));
        mmaf16(s11, aq1, (uint32_t)kB, (uint32_t)(kB >> 32));

        uint32_t paA[4], paB[4];
        paA[0] = ex2h2(f16x2_of(s00[0], s00[1]));
        paA[1] = ex2h2(f16x2_of(s00[2], s00[3]));
        paA[2] = ex2h2(f16x2_of(s01[0], s01[1]));
        paA[3] = ex2h2(f16x2_of(s01[2], s01[3]));
        paB[0] = ex2h2(f16x2_of(s10[0], s10[1]));
        paB[1] = ex2h2(f16x2_of(s10[2], s10[3]));
        paB[2] = ex2h2(f16x2_of(s11[0], s11[1]));
        paB[3] = ex2h2(f16x2_of(s11[2], s11[3]));

        // l accumulation on fma/alu pipes (quad-partial, reduced at end)
        {
            uint32_t cA0 = hadd2(paA[0], paA[2]);   // row g   (tile A)
            uint32_t cA1 = hadd2(paA[1], paA[3]);   // row g+8 (tile A)
            uint32_t cB0 = hadd2(paB[0], paB[2]);
            uint32_t cB1 = hadd2(paB[1], paB[3]);
            float lo, hi;
            f16x2_to_f32(cA0, lo, hi); lsA0 += lo + hi;
            f16x2_to_f32(cA1, lo, hi); lsA1 += lo + hi;
            f16x2_to_f32(cB0, lo, hi); lsB0 += lo + hi;
            f16x2_to_f32(cB1, lo, hi); lsB1 += lo + hi;
        }

        u64 vA = *vA_p, vB = *vB_p;
        vA_p += 64; vB_p += 64;
        mmaf16(dA0, paA, (uint32_t)vA, (uint32_t)(vA >> 32));
        mmaf16(dA1, paA, (uint32_t)vB, (uint32_t)(vB >> 32));
        mmaf16(dB0, paB, (uint32_t)vA, (uint32_t)(vA >> 32));
        mmaf16(dB1, paB, (uint32_t)vB, (uint32_t)(vB >> 32));
    }

    // quad reduce (lanes sharing g)
    #pragma unroll
    for (int m = 1; m <= 2; m <<= 1) {
        lsA0 += __shfl_xor_sync(0xFFFFFFFFu, lsA0, m);
        lsA1 += __shfl_xor_sync(0xFFFFFFFFu, lsA1, m);
        lsB0 += __shfl_xor_sync(0xFFFFFFFFu, lsB0, m);
        lsB1 += __shfl_xor_sync(0xFFFFFFFFu, lsB1, m);
    }

    float2* pn = g_pnum + ((size_t)(z * 64 + nh) * 8) * SP;
    float*  pd = g_pden + (size_t)(z * 64 + nh) * SP;

    #pragma unroll
    for (int tile = 0; tile < 2; tile++) {
        int qb = q0 + tile * 16;
        const float* d0 = tile ? dB0 : dA0;
        const float* d1 = tile ? dB1 : dA1;
        float l0 = tile ? lsB0 : lsA0;
        float l1 = tile ? lsB1 : lsA1;
        if (qb + g < SP) {
            pn[(size_t)t * SP + qb + g]       = make_float2(d0[0], d0[1]);
            pn[(size_t)(4 + t) * SP + qb + g] = make_float2(d1[0], d1[1]);
            if (t == 0) pd[qb + g] = l0;
        }
        if (qb + 8 + g < SP) {
            pn[(size_t)t * SP + qb + 8 + g]       = make_float2(d0[2], d0[3]);
            pn[(size_t)(4 + t) * SP + qb + 8 + g] = make_float2(d1[2], d1[3]);
            if (t == 0) pd[qb + 8 + g] = l1;
        }
    }
}

// ===================================================================
// Combine: add halves, divide, emit fragment-ready hi/lo g_op.
// ===================================================================
__global__ void attn_combine(void) {
    int idx = blockIdx.x * 256 + threadIdx.x;     // 64*1600 = 102400
    if (idx >= 64 * SP) return;
    int s = idx % SP;
    int nh = idx / SP;
    int n = nh >> 3, h = nh & 7;

    const float2* pn0 = g_pnum + (size_t)nh * 8 * SP;
    const float2* pn1 = g_pnum + (size_t)(64 + nh) * 8 * SP;
    float den = g_pden[(size_t)nh * SP + s] + g_pden[(size_t)(64 + nh) * SP + s];
    float inv = 1.f / den;

    ulonglong2 out[4];
    #pragma unroll
    for (int t = 0; t < 4; t++) {
        float2 a0 = pn0[(size_t)t * SP + s];
        float2 b0 = pn1[(size_t)t * SP + s];
        float2 a1 = pn0[(size_t)(4 + t) * SP + s];
        float2 b1 = pn1[(size_t)(4 + t) * SP + s];
        out[t].x = packh2((a0.x + b0.x) * inv, (a0.y + b0.y) * inv);
        out[t].y = packh2((a1.x + b1.x) * inv, (a1.y + b1.y) * inv);
    }
    ulonglong2* d = g_op + ((size_t)(n * SP + s) * 8 + h) * 4;
    d[0] = out[0]; d[1] = out[1]; d[2] = out[2]; d[3] = out[3];
}

// ===================================================================
extern "C" void kernel_launch(void* const* d_in, const int* in_sizes, int n_in,
                              void* d_out, int out_size) {
    const float* x     = (const float*)d_in[0];
    const float* w_qkv = (const float*)d_in[1];
    const float* w_o   = (const float*)d_in[2];
    const float* b_o   = (const float*)d_in[3];
    float* out = (float*)d_out;

    conv_all<<<(W_ITEMS + X_ITEMS + 255) / 256, 256>>>(w_qkv, w_o, x);
    proj_qkv_mma<<<dim3(SP / 64, 384 / 64, NB), 128>>>();
    attn_mma<<<dim3(13, NB * NHEAD, 2), 128>>>();
    attn_combine<<<(64 * SP + 255) / 256, 256>>>();
    proj_out_mma<<<dim3(SP / 64, CIN / 64, NB), 128>>>(b_o, out);
}

// round 17
// speedup vs baseline: 1.1086x; 1.1086x over previous
#include <cuda_runtime.h>
#include <cuda_fp16.h>
#include <cstdint>

#define NB    8
#define CIN   128
#define SP    1600
#define NHEAD 8
#define HD    16

typedef unsigned long long u64;

#define ONESH2 0x3C003C00u   // f16x2 (1.0, 1.0)

// f16x2 word: first arg -> low 16 bits, second -> high 16 bits
__device__ __forceinline__ uint32_t f16x2_of(float lo, float hi) {
    uint32_t r;
    asm("cvt.rn.f16x2.f32 %0, %1, %2;" : "=r"(r) : "f"(hi), "f"(lo));
    return r;
}
__device__ __forceinline__ void f16x2_to_f32(uint32_t w, float& lo, float& hi) {
    asm("{ .reg .b16 l, h; mov.b32 {l, h}, %2; cvt.f32.f16 %0, l; cvt.f32.f16 %1, h; }"
        : "=f"(lo), "=f"(hi) : "r"(w));
}
__device__ __forceinline__ u64 packh2(float a, float b) {
    uint32_t hw = f16x2_of(a, b);
    float ha, hb;
    f16x2_to_f32(hw, ha, hb);
    uint32_t lw = f16x2_of(a - ha, b - hb);
    return (u64)hw | ((u64)lw << 32);
}
__device__ __forceinline__ uint32_t ex2h2(uint32_t w) {
    uint32_t r; asm("ex2.approx.f16x2 %0, %1;" : "=r"(r) : "r"(w)); return r;
}

// warp mma: D += A(f16 16x16) * B(f16 16x8), f32 accum
__device__ __forceinline__ void mmaf16(float* d, const uint32_t* a, uint32_t b0, uint32_t b1) {
    asm volatile("mma.sync.aligned.m16n8k16.row.col.f32.f16.f16.f32 "
        "{%0,%1,%2,%3},{%4,%5,%6,%7},{%8,%9},{%0,%1,%2,%3};"
        : "+f"(d[0]), "+f"(d[1]), "+f"(d[2]), "+f"(d[3])
        : "r"(a[0]), "r"(a[1]), "r"(a[2]), "r"(a[3]), "r"(b0), "r"(b1));
}

// Scratch:
__device__ uint2      g_wp[(size_t)384 * 8 * 4];         // W_qkv f16 frags, PERMUTED rows
__device__ uint2      g_wop[(size_t)128 * 8 * 4];        // W_o   f16 frags, PERMUTED rows
__device__ ulonglong2 g_xp[(size_t)NB * SP * 8 * 4];     // X hi/lo frags [n][tok][ks][t]
__device__ ulonglong2 g_op[(size_t)NB * SP * 8 * 4];     // attn-out hi/lo frags [n][tok][ks=h][t]
__device__ uint32_t   g_qpk[(size_t)64 * 8 * SP + 64];   // Q f16x2 [nh][dpair][s]
__device__ u64        g_kp2[(size_t)64 * SP * 4];        // K frag words [nh][tok][4]
__device__ u64        g_vp2[(size_t)64 * 100 * 16 * 4];  // V frag words [nh][kt][dim][4]
__device__ float2     g_pnum[(size_t)2 * 64 * 8 * SP];   // partial numerators [z][nh][cp][s]
__device__ float      g_pden[(size_t)2 * 64 * SP];       // partial denominators [z][nh][s]

// ===================================================================
// Single conversion kernel: W_qkv + W_o (permuted rows) and X frags.
// ===================================================================
#define W_ITEMS (512 * 8)
#define X_ITEMS (NB * 8 * SP)

__global__ void conv_all(const float* __restrict__ Wq, const float* __restrict__ Wo,
                         const float* __restrict__ X) {
    int idx = blockIdx.x * 256 + threadIdx.x;
    if (idx < W_ITEMS) {
        int ks = idx & 7, r = idx >> 3;
        const float* W;
        uint2* dst;
        int rl;
        if (r < 384) { W = Wq; dst = g_wp;  rl = r; }
        else         { W = Wo; dst = g_wop; rl = r - 384; }
        int tile = rl >> 4, rr = rl & 15;
        int o = tile * 16 + ((rr < 8) ? 2 * rr : 2 * (rr - 8) + 1);
        const float* wr = W + (size_t)o * CIN + 16 * ks;
        uint2 out[4];
        #pragma unroll
        for (int t = 0; t < 4; t++) {
            out[t].x = f16x2_of(wr[2 * t],     wr[2 * t + 1]);
            out[t].y = f16x2_of(wr[2 * t + 8], wr[2 * t + 9]);
        }
        uint2* d = dst + ((size_t)rl * 8 + ks) * 4;
        d[0] = out[0]; d[1] = out[1]; d[2] = out[2]; d[3] = out[3];
    } else {
        int xi = idx - W_ITEMS;
        if (xi >= X_ITEMS) return;
        int s = xi % SP;
        int rest = xi / SP;
        int ks = rest & 7, n = rest >> 3;
        const float* xb = X + ((size_t)n * CIN + 16 * ks) * SP + s;
        ulonglong2 out[4];
        #pragma unroll
        for (int t = 0; t < 4; t++) {
            out[t].x = packh2(xb[(size_t)(2 * t) * SP],     xb[(size_t)(2 * t + 1) * SP]);
            out[t].y = packh2(xb[(size_t)(2 * t + 8) * SP], xb[(size_t)(2 * t + 9) * SP]);
        }
        ulonglong2* d = g_xp + ((size_t)(n * SP + s) * 8 + ks) * 4;
        d[0] = out[0]; d[1] = out[1]; d[2] = out[2]; d[3] = out[3];
    }
}

// ===================================================================
// Shared mainloop: X tile staged in SMEM (32KB), 2-term fp16 MMA.
// ===================================================================
__device__ __forceinline__ void proj_mainloop(
    char* sbuf, const uint2* __restrict__ Wf, const ulonglong2* __restrict__ Xf,
    int n, int s0, int o0, int tid, float d[8][4])
{
    const int warp = tid >> 5, lane = tid & 31;
    const int g = lane >> 2, t = lane & 3;

    ulonglong2* Xs = (ulonglong2*)sbuf;
    const ulonglong2* src = Xf + (size_t)(n * SP + s0) * 32;
    #pragma unroll
    for (int i = 0; i < 16; i++)
        Xs[tid + i * 128] = src[tid + i * 128];
    __syncthreads();

    const int r1 = o0 + warp * 16 + g;
    const int r2 = r1 + 8;

    #pragma unroll
    for (int ks = 0; ks < 8; ks++) {
        uint2 wa = Wf[((size_t)r1 * 8 + ks) * 4 + t];
        uint2 wb = Wf[((size_t)r2 * 8 + ks) * 4 + t];
        uint32_t ah[4] = {wa.x, wb.x, wa.y, wb.y};

        #pragma unroll
        for (int nb = 0; nb < 8; nb++) {
            ulonglong2 xv = Xs[((nb * 8 + g) * 8 + ks) * 4 + t];
            mmaf16(d[nb], ah, (uint32_t)xv.x, (uint32_t)xv.y);
            mmaf16(d[nb], ah, (uint32_t)(xv.x >> 32), (uint32_t)(xv.y >> 32));
        }
    }
}

// ===================================================================
// QKV projection: register-direct pack epilogue.
// ===================================================================
__global__ __launch_bounds__(128) void proj_qkv_mma(void) {
    __shared__ __align__(16) char sbuf[32768];

    const int n  = blockIdx.z;
    const int s0 = blockIdx.x * 64;
    const int o0 = blockIdx.y * 64;
    const int tid = threadIdx.x;
    const int warp = tid >> 5, lane = tid & 31;
    const int g = lane >> 2, t = lane & 3;

    float d[8][4];
    #pragma unroll
    for (int nb = 0; nb < 8; nb++)
        #pragma unroll
        for (int j = 0; j < 4; j++) d[nb][j] = 0.f;

    proj_mainloop(sbuf, g_wp, g_xp, n, s0, o0, tid, d);

    const float qs = 0.25f * 1.4426950408889634f;
    const int o_even = o0 + warp * 16 + 2 * g;
    const int hh = o_even / 48;
    const int within = o_even - hh * 48;
    const int nhI = n * 8 + hh;

    if (within < 16) {
        int dp = within >> 1;
        uint32_t* dst = g_qpk + ((size_t)nhI * 8 + dp) * SP;
        #pragma unroll
        for (int nb = 0; nb < 8; nb++) {
            int sa = s0 + nb * 8 + 2 * t;
            uint2 w;
            w.x = f16x2_of(d[nb][0] * qs, d[nb][2] * qs);
            w.y = f16x2_of(d[nb][1] * qs, d[nb][3] * qs);
            *(uint2*)(dst + sa) = w;
        }
    } else if (within < 32) {
        int dp = (within - 16) >> 1;
        int off = (dp & 3) * 2 + (dp >> 2);
        uint32_t* kb = (uint32_t*)g_kp2 + (size_t)nhI * SP * 8 + off;
        #pragma unroll
        for (int nb = 0; nb < 8; nb++) {
            int sa = s0 + nb * 8 + 2 * t;
            kb[(size_t)sa * 8]       = f16x2_of(d[nb][0], d[nb][2]);
            kb[(size_t)(sa + 1) * 8] = f16x2_of(d[nb][1], d[nb][3]);
        }
    } else {
        int dl = within - 32;
        uint32_t* vb = (uint32_t*)g_vp2 + (size_t)nhI * 100 * 128;
        #pragma unroll
        for (int nb = 0; nb < 8; nb++) {
            int tok = s0 + nb * 8 + 2 * t;
            int kt  = tok >> 4;
            int kpl = (tok >> 1) & 7;
            size_t base = (size_t)kt * 128 + (size_t)(kpl & 3) * 2 + (kpl >> 2);
            vb[base + (size_t)dl * 8]       = f16x2_of(d[nb][0], d[nb][1]);
            vb[base + (size_t)(dl + 1) * 8] = f16x2_of(d[nb][2], d[nb][3]);
        }
    }
}

// ===================================================================
// Output projection: permuted-row Ys staging + bias epilogue.
// ===================================================================
__global__ __launch_bounds__(128) void proj_out_mma(const float* __restrict__ bias,
                                                    float* __restrict__ Y) {
    __shared__ __align__(16) char sbuf[32768];

    const int n  = blockIdx.z;
    const int s0 = blockIdx.x * 64;
    const int o0 = blockIdx.y * 64;
    const int tid = threadIdx.x;
    const int warp = tid >> 5, lane = tid & 31;
    const int g = lane >> 2, t = lane & 3;

    float d[8][4];
    #pragma unroll
    for (int nb = 0; nb < 8; nb++)
        #pragma unroll
        for (int j = 0; j < 4; j++) d[nb][j] = 0.f;

    proj_mainloop(sbuf, g_wop, g_op, n, s0, o0, tid, d);
    __syncthreads();

    float (*Ys)[68] = (float(*)[68])sbuf;
    #pragma unroll
    for (int nb = 0; nb < 8; nb++) {
        int ol = warp * 16 + 2 * g;
        int sl = nb * 8 + 2 * t;
        Ys[ol][sl]     = d[nb][0];
        Ys[ol][sl + 1] = d[nb][1];
        Ys[ol + 1][sl]     = d[nb][2];
        Ys[ol + 1][sl + 1] = d[nb][3];
    }
    __syncthreads();

    const int tx = tid & 15, ty = tid >> 4;
    #pragma unroll
    for (int r = 0; r < 8; r++) {
        int olo = ty * 8 + r;
        int o = o0 + olo;
        float b = bias[o];
        float4 v = *(const float4*)&Ys[olo][tx * 4];
        v.x += b; v.y += b; v.z += b; v.w += b;
        *(float4*)(Y + ((size_t)n * CIN + o) * SP + s0 + tx * 4) = v;
    }
}

// ===================================================================
// Attention, key-split; l via ones-MMA (R15 proven form).
// ===================================================================
__global__ __launch_bounds__(128) void attn_mma(void) {
    const int tid  = threadIdx.x;
    const int warp = tid >> 5, lane = tid & 31;
    const int g = lane >> 2, t = lane & 3;
    const int nh = blockIdx.y;
    const int z  = blockIdx.z;
    const int q0 = blockIdx.x * 128 + warp * 32;

    const uint32_t* qp = g_qpk + (size_t)nh * 8 * SP;
    const u64* kp2 = g_kp2 + (size_t)nh * SP * 4;
    const u64* vp2 = g_vp2 + (size_t)nh * 100 * 64;

    uint32_t aq0[4], aq1[4];
    {
        const uint32_t* q1 = qp + (size_t)t * SP;
        const uint32_t* q2 = qp + (size_t)(t + 4) * SP;
        aq0[0] = q1[q0 + g];      aq0[1] = q1[q0 + 8 + g];
        aq0[2] = q2[q0 + g];      aq0[3] = q2[q0 + 8 + g];
        aq1[0] = q1[q0 + 16 + g]; aq1[1] = q1[q0 + 24 + g];
        aq1[2] = q2[q0 + 16 + g]; aq1[3] = q2[q0 + 24 + g];
    }

    float dA0[4] = {0,0,0,0}, dA1[4] = {0,0,0,0};
    float dB0[4] = {0,0,0,0}, dB1[4] = {0,0,0,0};
    float dLA[4] = {0,0,0,0}, dLB[4] = {0,0,0,0};

    const u64* kA_p = kp2 + (size_t)g * 4 + t;
    const u64* kB_p = kp2 + (size_t)(8 + g) * 4 + t;
    const u64* vA_p = vp2 + (size_t)g * 4 + t;
    const u64* vB_p = vp2 + (size_t)(8 + g) * 4 + t;

    const int kt0 = z * 50, kt1 = kt0 + 50;

    #pragma unroll 2
    for (int kt = kt0; kt < kt1; kt++) {
        u64 kA = kA_p[(size_t)kt * 64];
        u64 kB = kB_p[(size_t)kt * 64];

        float s00[4] = {0,0,0,0}, s01[4] = {0,0,0,0};
        float s10[4] = {0,0,0,0}, s11[4] = {0,0,0,0};
        mmaf16(s00, aq0, (uint32_t)kA, (uint32_t)(kA >> 32));
        mmaf16(s01, aq0, (uint32_t)kB, (uint32_t)(kB >> 32));
        mmaf16(s10, aq1, (uint32_t)kA, (uint32_t)(kA >> 32));
        mmaf16(s11, aq1, (uint32_t)kB, (uint32_t)(kB >> 32));

        uint32_t paA[4], paB[4];
        paA[0] = ex2h2(f16x2_of(s00[0], s00[1]));
        paA[1] = ex2h2(f16x2_of(s00[2], s00[3]));
        paA[2] = ex2h2(f16x2_of(s01[0], s01[1]));
        paA[3] = ex2h2(f16x2_of(s01[2], s01[3]));
        paB[0] = ex2h2(f16x2_of(s10[0], s10[1]));
        paB[1] = ex2h2(f16x2_of(s10[2], s10[3]));
        paB[2] = ex2h2(f16x2_of(s11[0], s11[1]));
        paB[3] = ex2h2(f16x2_of(s11[2], s11[3]));

        mmaf16(dLA, paA, ONESH2, ONESH2);
        mmaf16(dLB, paB, ONESH2, ONESH2);

        u64 vA = vA_p[(size_t)kt * 64];
        u64 vB = vB_p[(size_t)kt * 64];
        mmaf16(dA0, paA, (uint32_t)vA, (uint32_t)(vA >> 32));
        mmaf16(dA1, paA, (uint32_t)vB, (uint32_t)(vB >> 32));
        mmaf16(dB0, paB, (uint32_t)vA, (uint32_t)(vA >> 32));
        mmaf16(dB1, paB, (uint32_t)vB, (uint32_t)(vB >> 32));
    }

    float2* pn = g_pnum + ((size_t)(z * 64 + nh) * 8) * SP;
    float*  pd = g_pden + (size_t)(z * 64 + nh) * SP;

    #pragma unroll
    for (int tile = 0; tile < 2; tile++) {
        int qb = q0 + tile * 16;
        const float* d0 = tile ? dB0 : dA0;
        const float* d1 = tile ? dB1 : dA1;
        const float* dL = tile ? dLB : dLA;
        if (qb + g < SP) {
            pn[(size_t)t * SP + qb + g]       = make_float2(d0[0], d0[1]);
            pn[(size_t)(4 + t) * SP + qb + g] = make_float2(d1[0], d1[1]);
            if (t == 0) pd[qb + g] = dL[0];
        }
        if (qb + 8 + g < SP) {
            pn[(size_t)t * SP + qb + 8 + g]       = make_float2(d0[2], d0[3]);
            pn[(size_t)(4 + t) * SP + qb + 8 + g] = make_float2(d1[2], d1[3]);
            if (t == 0) pd[qb + 8 + g] = dL[2];
        }
    }
}

// ===================================================================
// Combine: 4x parallelism — one thread per (nh, t, s).
// ===================================================================
__global__ void attn_combine(void) {
    int idx = blockIdx.x * 256 + threadIdx.x;     // 64*4*1600 = 409600
    if (idx >= 64 * 4 * SP) return;
    int s = idx % SP;
    int rest = idx / SP;
    int t = rest & 3;
    int nh = rest >> 2;
    int n = nh >> 3, h = nh & 7;

    const float2* pn0 = g_pnum + (size_t)nh * 8 * SP;
    const float2* pn1 = g_pnum + (size_t)(64 + nh) * 8 * SP;
    float den = g_pden[(size_t)nh * SP + s] + g_pden[(size_t)(64 + nh) * SP + s];
    float inv = 1.f / den;

    float2 a0 = pn0[(size_t)t * SP + s];
    float2 b0 = pn1[(size_t)t * SP + s];
    float2 a1 = pn0[(size_t)(4 + t) * SP + s];
    float2 b1 = pn1[(size_t)(4 + t) * SP + s];

    ulonglong2 out;
    out.x = packh2((a0.x + b0.x) * inv, (a0.y + b0.y) * inv);
    out.y = packh2((a1.x + b1.x) * inv, (a1.y + b1.y) * inv);
    g_op[((size_t)(n * SP + s) * 8 + h) * 4 + t] = out;
}

// ===================================================================
extern "C" void kernel_launch(void* const* d_in, const int* in_sizes, int n_in,
                              void* d_out, int out_size) {
    const float* x     = (const float*)d_in[0];
    const float* w_qkv = (const float*)d_in[1];
    const float* w_o   = (const float*)d_in[2];
    const float* b_o   = (const float*)d_in[3];
    float* out = (float*)d_out;

    conv_all<<<(W_ITEMS + X_ITEMS + 255) / 256, 256>>>(w_qkv, w_o, x);
    proj_qkv_mma<<<dim3(SP / 64, 384 / 64, NB), 128>>>();
    attn_mma<<<dim3(13, NB * NHEAD, 2), 128>>>();
    attn_combine<<<(64 * 4 * SP + 255) / 256, 256>>>();
    proj_out_mma<<<dim3(SP / 64, CIN / 64, NB), 128>>>(b_o, out);
}